// round 9
// baseline (speedup 1.0000x reference)
#include <cuda_runtime.h>
#include <math.h>

#define DIM 1024
#define WARPS 4
#define NTHREADS (WARPS * 32)
#define GRID_BLOCKS 760
#define NSLOT 2

// ---- TMA bulk-store helpers (S2G, bulk_group) ----
__device__ __forceinline__ void bulk_store_4k(void* gdst, const void* ssrc) {
    unsigned saddr = (unsigned)__cvta_generic_to_shared(ssrc);
    asm volatile("cp.async.bulk.global.shared::cta.bulk_group [%0], [%1], %2;"
                 :: "l"(gdst), "r"(saddr), "r"(4096) : "memory");
}
__device__ __forceinline__ void bulk_commit() {
    asm volatile("cp.async.bulk.commit_group;" ::: "memory");
}
template<int N> __device__ __forceinline__ void bulk_wait_read() {
    asm volatile("cp.async.bulk.wait_group.read %0;" :: "n"(N) : "memory");
}
__device__ __forceinline__ void fence_async_proxy() {
    asm volatile("fence.proxy.async.shared::cta;" ::: "memory");
}

__global__ __launch_bounds__(NTHREADS)
void iln_tma(const float* __restrict__ x,
             const float* __restrict__ weight,
             const float* __restrict__ bias,
             float* __restrict__ out,
             int n_rows)
{
    __shared__ float4 s_out[WARPS][NSLOT][DIM / 4];   // 32 KB staging
    __shared__ int4 s_wb[DIM / 4];                     // packed int16 w/b, 4 KB
    __shared__ int s_lut[32];

    const int tid  = threadIdx.x;
    const int warp = tid >> 5;
    const int lane = tid & 31;

    // 32-entry isqrt LUT, exact: round((1<<15)/sqrt(2^parity*(1+m/16)))
    if (tid < 32) {
        const int parity = tid >> 4;
        const int mant = tid & 15;
        const double val = (double)(1 << parity) * (1.0 + (double)mant * 0.0625);
        s_lut[tid] = (int)llrint(32768.0 / sqrt(val));
    }
    // Packed quantized weight/bias (round-half-even matches jnp.round)
    for (int i = tid; i < DIM / 4; i += NTHREADS) {
        const float4 w4 = ((const float4*)weight)[i];
        const float4 b4 = ((const float4*)bias)[i];
        const int w0 = __float2int_rn(w4.x * 256.0f);
        const int w1 = __float2int_rn(w4.y * 256.0f);
        const int w2 = __float2int_rn(w4.z * 256.0f);
        const int w3 = __float2int_rn(w4.w * 256.0f);
        const int b0 = __float2int_rn(b4.x * 256.0f);
        const int b1 = __float2int_rn(b4.y * 256.0f);
        const int b2 = __float2int_rn(b4.z * 256.0f);
        const int b3 = __float2int_rn(b4.w * 256.0f);
        s_wb[i] = make_int4((w0 & 0xffff) | (w1 << 16),
                            (w2 & 0xffff) | (w3 << 16),
                            (b0 & 0xffff) | (b1 << 16),
                            (b2 & 0xffff) | (b3 << 16));
    }
    __syncthreads();

    const int gw = blockIdx.x * WARPS + warp;      // global warp id
    const int stride = GRID_BLOCKS * WARPS;
    int slot = 0;

    for (int row = gw; row < n_rows; row += stride) {
        const float4* __restrict__ xr = (const float4*)(x + (size_t)row * DIM);

        // ---- front-batched reads: 8 independent LDG.128 (proven ~4.3 TB/s path) ----
        float4 v[8];
        #pragma unroll
        for (int j = 0; j < 8; j++) v[j] = xr[j * 32 + lane];

        int xi[32];
        int sum = 0, sumsq = 0;                     // row sumsq ~1e8 << 2^31, exact
        #pragma unroll
        for (int j = 0; j < 8; j++) {
            const int a0 = __float2int_rn(v[j].x);
            const int a1 = __float2int_rn(v[j].y);
            const int a2 = __float2int_rn(v[j].z);
            const int a3 = __float2int_rn(v[j].w);
            xi[j * 4 + 0] = a0; xi[j * 4 + 1] = a1;
            xi[j * 4 + 2] = a2; xi[j * 4 + 3] = a3;
            sum   += a0 + a1 + a2 + a3;
            sumsq += a0 * a0 + a1 * a1 + a2 * a2 + a3 * a3;
        }
        sum   = __reduce_add_sync(0xffffffffu, sum);
        sumsq = __reduce_add_sync(0xffffffffu, sumsq);

        const int mean = (sum * 64) >> 16;          // fixed-point mean
        const long long ssy = (long long)sumsq
                            - 2LL * (long long)mean * (long long)sum
                            + (long long)DIM * (long long)mean * (long long)mean;
        long long var = (ssy * 64) >> 16;
        if (var < 1) var = 1;
        const int k = 63 - __clzll((unsigned long long)var);   // floor(log2), exact
        const int sa = k - 4;
        const int mant = (sa >= 0) ? (int)((var >> sa) & 15)
                                   : (int)((var << (-sa)) & 15);
        const int inv = s_lut[((k & 1) << 4) | mant];
        const int ts = (k >> 1) + 15;               // p + SHIFT(0) + Q_LUT(15)

        // ---- make sure this slot's previous bulk store has released the smem ----
        if (lane == 0) bulk_wait_read<1>();
        __syncwarp();

        // ---- epilogue into smem staging slot ----
        float4* __restrict__ dst = s_out[warp][slot];
        #pragma unroll
        for (int j = 0; j < 8; j++) {
            const int4 wb = s_wb[j * 32 + lane];
            const int w0 = (wb.x << 16) >> 16, w1 = wb.x >> 16;
            const int w2 = (wb.y << 16) >> 16, w3 = wb.y >> 16;
            const int b0 = (wb.z << 16) >> 16, b1 = wb.z >> 16;
            const int b2 = (wb.w << 16) >> 16, b3 = wb.w >> 16;
            float4 o;
            long long t;
            t = (((long long)((xi[j*4+0] - mean) * inv) * (long long)w0) >> ts) + b0;
            o.x = (float)t * 0.00390625f;
            t = (((long long)((xi[j*4+1] - mean) * inv) * (long long)w1) >> ts) + b1;
            o.y = (float)t * 0.00390625f;
            t = (((long long)((xi[j*4+2] - mean) * inv) * (long long)w2) >> ts) + b2;
            o.z = (float)t * 0.00390625f;
            t = (((long long)((xi[j*4+3] - mean) * inv) * (long long)w3) >> ts) + b3;
            o.w = (float)t * 0.00390625f;
            dst[j * 32 + lane] = o;                 // STS.128
        }
        __syncwarp();

        // ---- one contiguous 4 KB engine-driven write burst per row ----
        if (lane == 0) {
            fence_async_proxy();
            bulk_store_4k(out + (size_t)row * DIM, dst);
            bulk_commit();
        }
        slot ^= 1;
    }

    if (lane == 0) bulk_wait_read<0>();             // drain before exit
}

extern "C" void kernel_launch(void* const* d_in, const int* in_sizes, int n_in,
                              void* d_out, int out_size) {
    const float* x      = (const float*)d_in[0];
    const float* weight = (const float*)d_in[1];
    const float* bias   = (const float*)d_in[2];
    // d_in[3] (isqrt_lut) intentionally unused: LUT recomputed exactly in-kernel.
    float* out = (float*)d_out;

    const int n_rows = in_sizes[0] / DIM;
    iln_tma<<<GRID_BLOCKS, NTHREADS>>>(x, weight, bias, out, n_rows);
}

// round 10
// speedup vs baseline: 1.9382x; 1.9382x over previous
#include <cuda_runtime.h>
#include <math.h>

#define DIM 1024
#define WARPS_PER_BLOCK 4
#define NTHREADS 128
#define GRID_BLOCKS 760          // ~5 blocks * 152 SMs
#define F4_PER_ROW 256
#define NSTAGE 2

__device__ __forceinline__ void cp_async16(void* smem_dst, const void* gsrc) {
    unsigned saddr = (unsigned)__cvta_generic_to_shared(smem_dst);
    asm volatile("cp.async.cg.shared.global [%0], [%1], 16;\n" :: "r"(saddr), "l"(gsrc));
}
__device__ __forceinline__ void cp_commit() { asm volatile("cp.async.commit_group;\n"); }
template<int N> __device__ __forceinline__ void cp_wait() {
    asm volatile("cp.async.wait_group %0;\n" :: "n"(N));
}

__global__ __launch_bounds__(NTHREADS)
void iln_kernel(const float* __restrict__ x,
                const float* __restrict__ weight,
                const float* __restrict__ bias,
                float* __restrict__ out,
                int n_rows)
{
    __shared__ int s_w[DIM];
    __shared__ int s_b[DIM];
    __shared__ int s_lut[32];
    __shared__ float4 s_x[WARPS_PER_BLOCK][NSTAGE][F4_PER_ROW];

    const int tid = threadIdx.x;

    // 32-entry isqrt LUT, exact: round((1<<15)/sqrt(2^parity*(1+m/16)))
    if (tid < 32) {
        const int parity = tid >> 4;
        const int mant = tid & 15;
        const double val = (double)(1 << parity) * (1.0 + (double)mant * 0.0625);
        s_lut[tid] = (int)llrint(32768.0 / sqrt(val));
    }
    // Quantize weight/bias (round-half-even matches jnp.round)
    for (int i = tid; i < DIM; i += NTHREADS) {
        s_w[i] = __float2int_rn(weight[i] * 256.0f);
        s_b[i] = __float2int_rn(bias[i] * 256.0f);
    }
    __syncthreads();

    const int warp = tid >> 5;
    const int lane = tid & 31;
    const int stride = GRID_BLOCKS * WARPS_PER_BLOCK;
    int row = blockIdx.x * WARPS_PER_BLOCK + warp;

    // Prologue prefetch
    if (row < n_rows) {
        const float4* __restrict__ xr = (const float4*)(x + (size_t)row * DIM);
        #pragma unroll
        for (int j = 0; j < 8; j++)
            cp_async16(&s_x[warp][0][j * 32 + lane], &xr[j * 32 + lane]);
        cp_commit();
    }

    int cur = 0;
    for (; row < n_rows; row += stride) {
        const int nxt = row + stride;
        if (nxt < n_rows) {
            const float4* __restrict__ xn = (const float4*)(x + (size_t)nxt * DIM);
            #pragma unroll
            for (int j = 0; j < 8; j++)
                cp_async16(&s_x[warp][cur ^ 1][j * 32 + lane], &xn[j * 32 + lane]);
            cp_commit();
            cp_wait<1>();        // wait only for the *current* row's group
        } else {
            cp_wait<0>();
        }

        // ---- phase 1: smem -> int regs, partial sums ----
        int xi[32];
        int sum = 0, sumsq = 0;  // row sumsq ~1e8 << 2^31, exact
        #pragma unroll
        for (int j = 0; j < 8; j++) {
            const float4 v = s_x[warp][cur][j * 32 + lane];
            const int a0 = __float2int_rn(v.x);
            const int a1 = __float2int_rn(v.y);
            const int a2 = __float2int_rn(v.z);
            const int a3 = __float2int_rn(v.w);
            xi[j * 4 + 0] = a0; xi[j * 4 + 1] = a1;
            xi[j * 4 + 2] = a2; xi[j * 4 + 3] = a3;
            sum   += a0 + a1 + a2 + a3;
            sumsq += a0 * a0 + a1 * a1 + a2 * a2 + a3 * a3;
        }

        sum   = __reduce_add_sync(0xffffffffu, sum);
        sumsq = __reduce_add_sync(0xffffffffu, sumsq);

        const int mean = (sum * 64) >> 16;                 // fixed-point mean
        const long long ssy = (long long)sumsq
                            - 2LL * (long long)mean * (long long)sum
                            + (long long)DIM * (long long)mean * (long long)mean;
        long long var = (ssy * 64) >> 16;
        if (var < 1) var = 1;

        const int k = 63 - __clzll((unsigned long long)var);   // floor(log2), exact
        const int sa = k - 4;
        const int mant = (sa >= 0) ? (int)((var >> sa) & 15)
                                   : (int)((var << (-sa)) & 15);
        const int inv = s_lut[((k & 1) << 4) | mant];
        const int ts = (k >> 1) + 15;      // p + SHIFT(0) + Q_LUT(15), 15 <= ts <= ~24
        const int minv = mean * inv;       // hoisted: s = a*inv - minv (1 IMAD/elem)

        float4* __restrict__ orow = (float4*)(out + (size_t)row * DIM);
        #pragma unroll
        for (int j = 0; j < 8; j++) {
            const int c4 = j * 32 + lane;
            const int4 w4 = ((const int4*)s_w)[c4];
            const int4 b4 = ((const int4*)s_b)[c4];
            float4 o;
            // per element: IMAD, IMAD.WIDE(lo,hi), SHF(funnel), IADD, I2F.S32, FMUL
            {
                const int s = xi[j*4+0] * inv - minv;
                const int lo = s * w4.x, hi = __mulhi(s, w4.x);
                o.x = (float)((int)__funnelshift_r((unsigned)lo, (unsigned)hi, ts) + b4.x)
                      * 0.00390625f;
            }
            {
                const int s = xi[j*4+1] * inv - minv;
                const int lo = s * w4.y, hi = __mulhi(s, w4.y);
                o.y = (float)((int)__funnelshift_r((unsigned)lo, (unsigned)hi, ts) + b4.y)
                      * 0.00390625f;
            }
            {
                const int s = xi[j*4+2] * inv - minv;
                const int lo = s * w4.z, hi = __mulhi(s, w4.z);
                o.z = (float)((int)__funnelshift_r((unsigned)lo, (unsigned)hi, ts) + b4.z)
                      * 0.00390625f;
            }
            {
                const int s = xi[j*4+3] * inv - minv;
                const int lo = s * w4.w, hi = __mulhi(s, w4.w);
                o.w = (float)((int)__funnelshift_r((unsigned)lo, (unsigned)hi, ts) + b4.w)
                      * 0.00390625f;
            }
            __stcs(&orow[c4], o);
        }

        cur ^= 1;
    }
}

extern "C" void kernel_launch(void* const* d_in, const int* in_sizes, int n_in,
                              void* d_out, int out_size) {
    const float* x      = (const float*)d_in[0];
    const float* weight = (const float*)d_in[1];
    const float* bias   = (const float*)d_in[2];
    // d_in[3] (isqrt_lut) intentionally unused: LUT recomputed exactly in-kernel.
    float* out = (float*)d_out;

    const int n_rows = in_sizes[0] / DIM;
    iln_kernel<<<GRID_BLOCKS, NTHREADS>>>(x, weight, bias, out, n_rows);
}

// round 11
// speedup vs baseline: 1.9624x; 1.0125x over previous
#include <cuda_runtime.h>
#include <math.h>

#define DIM 1024
#define WARPS_PER_BLOCK 4
#define NTHREADS 128
#define GRID_BLOCKS 760          // ~5 blocks * 152 SMs
#define F4_PER_ROW 256
#define NSTAGE 2

__device__ __forceinline__ void cp_async16(void* smem_dst, const void* gsrc) {
    unsigned saddr = (unsigned)__cvta_generic_to_shared(smem_dst);
    asm volatile("cp.async.cg.shared.global [%0], [%1], 16;\n" :: "r"(saddr), "l"(gsrc));
}
__device__ __forceinline__ void cp_commit() { asm volatile("cp.async.commit_group;\n"); }
template<int N> __device__ __forceinline__ void cp_wait() {
    asm volatile("cp.async.wait_group %0;\n" :: "n"(N));
}

__global__ __launch_bounds__(NTHREADS)
void iln_kernel(const float* __restrict__ x,
                const float* __restrict__ weight,
                const float* __restrict__ bias,
                float* __restrict__ out,
                int n_rows)
{
    __shared__ int   s_w[DIM];
    __shared__ float s_fb[DIM];          // bias_int / 256 as float (exact)
    __shared__ int   s_lut[32];
    __shared__ float4 s_x[WARPS_PER_BLOCK][NSTAGE][F4_PER_ROW];

    const int tid = threadIdx.x;

    // 32-entry isqrt LUT, exact: round((1<<15)/sqrt(2^parity*(1+m/16)))
    if (tid < 32) {
        const int parity = tid >> 4;
        const int mant = tid & 15;
        const double val = (double)(1 << parity) * (1.0 + (double)mant * 0.0625);
        s_lut[tid] = (int)llrint(32768.0 / sqrt(val));
    }
    // Quantize weight/bias (round-half-even matches jnp.round).
    // fb = bias_int/256 exactly representable in fp32 (|b_int| small, /256 = 2^-8).
    for (int i = tid; i < DIM; i += NTHREADS) {
        s_w[i]  = __float2int_rn(weight[i] * 256.0f);
        s_fb[i] = (float)__float2int_rn(bias[i] * 256.0f) * 0.00390625f;
    }
    __syncthreads();

    const int warp = tid >> 5;
    const int lane = tid & 31;
    const int stride = GRID_BLOCKS * WARPS_PER_BLOCK;
    int row = blockIdx.x * WARPS_PER_BLOCK + warp;

    // Prologue prefetch
    if (row < n_rows) {
        const float4* __restrict__ xr = (const float4*)(x + (size_t)row * DIM);
        #pragma unroll
        for (int j = 0; j < 8; j++)
            cp_async16(&s_x[warp][0][j * 32 + lane], &xr[j * 32 + lane]);
        cp_commit();
    }

    int cur = 0;
    for (; row < n_rows; row += stride) {
        const int nxt = row + stride;
        if (nxt < n_rows) {
            const float4* __restrict__ xn = (const float4*)(x + (size_t)nxt * DIM);
            #pragma unroll
            for (int j = 0; j < 8; j++)
                cp_async16(&s_x[warp][cur ^ 1][j * 32 + lane], &xn[j * 32 + lane]);
            cp_commit();
            cp_wait<1>();        // wait only for the *current* row's group
        } else {
            cp_wait<0>();
        }

        // ---- phase 1: smem -> int regs, partial sums ----
        int xi[32];
        int sum = 0, sumsq = 0;  // row sumsq ~1e8 << 2^31, exact
        #pragma unroll
        for (int j = 0; j < 8; j++) {
            const float4 v = s_x[warp][cur][j * 32 + lane];
            const int a0 = __float2int_rn(v.x);
            const int a1 = __float2int_rn(v.y);
            const int a2 = __float2int_rn(v.z);
            const int a3 = __float2int_rn(v.w);
            xi[j * 4 + 0] = a0; xi[j * 4 + 1] = a1;
            xi[j * 4 + 2] = a2; xi[j * 4 + 3] = a3;
            sum   += a0 + a1 + a2 + a3;
            sumsq += a0 * a0 + a1 * a1 + a2 * a2 + a3 * a3;
        }

        sum   = __reduce_add_sync(0xffffffffu, sum);
        sumsq = __reduce_add_sync(0xffffffffu, sumsq);

        const int mean = (sum * 64) >> 16;                 // fixed-point mean
        const long long ssy = (long long)sumsq
                            - 2LL * (long long)mean * (long long)sum
                            + (long long)DIM * (long long)mean * (long long)mean;
        long long var = (ssy * 64) >> 16;
        if (var < 1) var = 1;

        const int k = 63 - __clzll((unsigned long long)var);   // floor(log2), exact
        const int sa = k - 4;
        const int mant = (sa >= 0) ? (int)((var >> sa) & 15)
                                   : (int)((var << (-sa)) & 15);
        const int inv = s_lut[((k & 1) << 4) | mant];
        const int ts = (k >> 1) + 15;      // p + SHIFT(0) + Q_LUT(15), ts in [15, ~24]
        const int minv = mean * inv;       // hoisted: s = a*inv - minv (1 IMAD/elem)

        float4* __restrict__ orow = (float4*)(out + (size_t)row * DIM);
        #pragma unroll
        for (int j = 0; j < 8; j++) {
            const int c4 = j * 32 + lane;
            const int4   w4 = ((const int4*)s_w)[c4];
            const float4 f4 = ((const float4*)s_fb)[c4];
            float4 o;
            // per element: IMAD, IMAD.WIDE, SHF, I2F, FFMA  (exact; see proof in R10/R11 notes)
            {
                const int s = xi[j*4+0] * inv - minv;
                const int lo = s * w4.x, hi = __mulhi(s, w4.x);
                o.x = fmaf((float)(int)__funnelshift_r((unsigned)lo, (unsigned)hi, ts),
                           0.00390625f, f4.x);
            }
            {
                const int s = xi[j*4+1] * inv - minv;
                const int lo = s * w4.y, hi = __mulhi(s, w4.y);
                o.y = fmaf((float)(int)__funnelshift_r((unsigned)lo, (unsigned)hi, ts),
                           0.00390625f, f4.y);
            }
            {
                const int s = xi[j*4+2] * inv - minv;
                const int lo = s * w4.z, hi = __mulhi(s, w4.z);
                o.z = fmaf((float)(int)__funnelshift_r((unsigned)lo, (unsigned)hi, ts),
                           0.00390625f, f4.z);
            }
            {
                const int s = xi[j*4+3] * inv - minv;
                const int lo = s * w4.w, hi = __mulhi(s, w4.w);
                o.w = fmaf((float)(int)__funnelshift_r((unsigned)lo, (unsigned)hi, ts),
                           0.00390625f, f4.w);
            }
            __stcs(&orow[c4], o);
        }

        cur ^= 1;
    }
}

extern "C" void kernel_launch(void* const* d_in, const int* in_sizes, int n_in,
                              void* d_out, int out_size) {
    const float* x      = (const float*)d_in[0];
    const float* weight = (const float*)d_in[1];
    const float* bias   = (const float*)d_in[2];
    // d_in[3] (isqrt_lut) intentionally unused: LUT recomputed exactly in-kernel.
    float* out = (float*)d_out;

    const int n_rows = in_sizes[0] / DIM;
    iln_kernel<<<GRID_BLOCKS, NTHREADS>>>(x, weight, bias, out, n_rows);
}